// round 12
// baseline (speedup 1.0000x reference)
#include <cuda_runtime.h>
#include <cstdint>

// ---------------------------------------------------------------------------
// QuadTreeDecoder round 12
//  Level-4 algebra from R11 (validated), restructured into streaming kernels:
//   qt_stack: per (p4): [fi4s | fi5s x4 | W] . x4 -> LAT4, F5X, WX  (one x pass)
//   qt_final: lat-space only: lat5 = F5X + G.lat4; y = WX + WFA.lat4 + WF5_c.lat5
//  No mid-kernel staging loops, no phase syncs in the hot path.
// ---------------------------------------------------------------------------

typedef unsigned long long u64;

__device__ float4 g_x2[(size_t)16  * 16 * 128];
__device__ float4 g_x4[(size_t)256 * 16 * 128];
__device__ float  g_wf[(size_t)1024 * 4 * 48 * 16];   // WF5[cn][c][48][16]
__device__ float  g_wfa[(size_t)1024 * 48 * 16];      // WFA[cn][48][16]
__device__ float  g_g[(size_t)1024 * 16 * 16];        // G[cn][16][16]
__device__ float  g_lat4[(size_t)256 * 16 * 128];     // LAT4[p4][r][b]
__device__ float  g_f5x[(size_t)1024 * 16 * 128];     // F5X[cn][r][b]
__device__ float  g_wx[(size_t)256 * 48 * 128];       // WX[p4][k][b]

// ---------------------------------------------------------------------------
__device__ __forceinline__ void fma2(u64& d, u64 a, u64 b) {
    asm("fma.rn.f32x2 %0, %1, %2, %3;" : "=l"(d) : "l"(a), "l"(b), "l"(d));
}
__device__ __forceinline__ u64 pack2(float lo, float hi) {
    u64 r; asm("mov.b64 %0, {%1, %2};" : "=l"(r) : "f"(lo), "f"(hi)); return r;
}
__device__ __forceinline__ float fold2(u64 v) {
    float lo, hi; asm("mov.b64 {%0, %1}, %2;" : "=f"(lo), "=f"(hi) : "l"(v));
    return lo + hi;
}

// ---------------------------------------------------------------------------
__device__ __forceinline__ void stage_factor_n(float dst[16][64], const float* __restrict__ src,
                                               const float* __restrict__ sc, int tid, int nthr)
{
    const float4* s4 = (const float4*)src;
    float4* d4 = (float4*)dst;
    if (sc) {
        for (int idx = tid; idx < 256; idx += nthr) {
            float4 v = s4[idx];
            float s = __ldg(&sc[idx >> 4]);
            v.x *= s; v.y *= s; v.z *= s; v.w *= s;
            d4[idx] = v;
        }
    } else {
        for (int idx = tid; idx < 256; idx += nthr)
            d4[idx] = s4[idx];
    }
}

__device__ __forceinline__ void lat_from_smem(float lat[16],
        const float (*__restrict__ fi)[64], const float4 (*__restrict__ x_s)[64], int col)
{
    u64 acc[16];
#pragma unroll
    for (int r = 0; r < 16; r++) acc[r] = 0ull;
#pragma unroll 4
    for (int i4 = 0; i4 < 16; i4++) {
        ulonglong2 xv = *(const ulonglong2*)&x_s[i4][col];
#pragma unroll
        for (int r = 0; r < 16; r++) {
            ulonglong2 f = *(const ulonglong2*)&fi[r][i4 * 4];
            fma2(acc[r], xv.x, f.x);
            fma2(acc[r], xv.y, f.y);
        }
    }
#pragma unroll
    for (int r = 0; r < 16; r++) lat[r] = fold2(acc[r]);
}

__device__ __forceinline__ void duppack16(u64 lp[16], const float lat[16]) {
#pragma unroll
    for (int r = 0; r < 16; r++) lp[r] = pack2(lat[r], lat[r]);
}

__device__ __forceinline__ void update_smem(float4 (*x_s)[64],
        const float (*__restrict__ F)[64], const u64 lp[16], int col)
{
#pragma unroll 4
    for (int o4 = 0; o4 < 16; o4++) {
        ulonglong2 a = *(const ulonglong2*)&x_s[o4][col];
#pragma unroll
        for (int r = 0; r < 16; r++) {
            ulonglong2 f = *(const ulonglong2*)&F[r][o4 * 4];
            fma2(a.x, lp[r], f.x);
            fma2(a.y, lp[r], f.y);
        }
        *(ulonglong2*)&x_s[o4][col] = a;
    }
}

__device__ __forceinline__ void emit_global(float4* __restrict__ op,
        const float4 (*__restrict__ x_s)[64],
        const float (*__restrict__ F)[64], const u64 lp[16], int col)
{
#pragma unroll 4
    for (int o4 = 0; o4 < 16; o4++) {
        ulonglong2 a = *(const ulonglong2*)&x_s[o4][col];
#pragma unroll
        for (int r = 0; r < 16; r++) {
            ulonglong2 f = *(const ulonglong2*)&F[r][o4 * 4];
            fma2(a.x, lp[r], f.x);
            fma2(a.y, lp[r], f.y);
        }
        *(ulonglong2*)&op[o4 * 128] = a;
    }
}

// ---------------------------------------------------------------------------
// WF5[cn][c][k][r] = sum_o head_w[k][o] * F_c[341+cn][r][o].  4096 blocks x 64.
// ---------------------------------------------------------------------------
__global__ __launch_bounds__(64)
void qt_wf_kernel(const float* __restrict__ ftl, const float* __restrict__ ftr,
                  const float* __restrict__ fbl, const float* __restrict__ fbr,
                  const float* __restrict__ head_w, float* __restrict__ wf)
{
    __shared__ __align__(16) float F_s[16][64];

    const int bid = blockIdx.x;
    const int p   = bid >> 2;
    const int c   = bid & 3;
    const int tid = threadIdx.x;
    const int node = 341 + p;

    const float* Fc = (c == 0 ? ftl : c == 1 ? ftr : c == 2 ? fbl : fbr)
                      + (size_t)node * 1024;
    stage_factor_n(F_s, Fc, nullptr, tid, 64);
    __syncthreads();

    if (tid < 48) {
        const int k = tid;
        const ulonglong2* wrow = (const ulonglong2*)(head_w + (size_t)k * 64);
        u64 acc[16];
#pragma unroll
        for (int r = 0; r < 16; r++) acc[r] = 0ull;
#pragma unroll 4
        for (int i4 = 0; i4 < 16; i4++) {
            ulonglong2 wv = __ldg(&wrow[i4]);
#pragma unroll
            for (int r = 0; r < 16; r++) {
                ulonglong2 f = *(const ulonglong2*)&F_s[r][i4 * 4];
                fma2(acc[r], wv.x, f.x);
                fma2(acc[r], wv.y, f.y);
            }
        }
        float* dst = wf + ((size_t)p * 4 + c) * (48 * 16) + (size_t)k * 16;
#pragma unroll
        for (int r = 0; r < 16; r += 4)
            *(float4*)(dst + r) = make_float4(fold2(acc[r]), fold2(acc[r+1]),
                                              fold2(acc[r+2]), fold2(acc[r+3]));
    }
}

// ---------------------------------------------------------------------------
// WFA[cn][k][r4] = sum_o W[k][o] * F4_{c4}[85+p4][r4][o]
// G  [cn][r][r4] = sum_o fi5s[341+cn][r][o] * F4_{c4}[85+p4][r4][o]
// ---------------------------------------------------------------------------
__global__ __launch_bounds__(64)
void qt_wfa_g_kernel(const float* __restrict__ ftl, const float* __restrict__ ftr,
                     const float* __restrict__ fbl, const float* __restrict__ fbr,
                     const float* __restrict__ fin, const float* __restrict__ scale,
                     const float* __restrict__ head_w,
                     float* __restrict__ wfa, float* __restrict__ gg)
{
    __shared__ __align__(16) float F_s[16][64];
    __shared__ __align__(16) float fi5s[16][64];

    const int cn  = blockIdx.x;
    const int tid = threadIdx.x;
    const int r5 = cn >> 5, c5 = cn & 31;
    const int p4 = (r5 >> 1) * 16 + (c5 >> 1);
    const int c4 = ((r5 & 1) << 1) | (c5 & 1);
    const int nodeA = 85 + p4;
    const int nodeB = 341 + cn;

    const float* Fc = (c4 == 0 ? ftl : c4 == 1 ? ftr : c4 == 2 ? fbl : fbr)
                      + (size_t)nodeA * 1024;
    stage_factor_n(F_s, Fc, nullptr, tid, 64);
    stage_factor_n(fi5s, fin + (size_t)nodeB * 1024, scale + (size_t)nodeB * 16, tid, 64);
    __syncthreads();

    if (tid < 48) {
        const int k = tid;
        const ulonglong2* wrow = (const ulonglong2*)(head_w + (size_t)k * 64);
        u64 acc[16];
#pragma unroll
        for (int r = 0; r < 16; r++) acc[r] = 0ull;
#pragma unroll 4
        for (int i4 = 0; i4 < 16; i4++) {
            ulonglong2 wv = __ldg(&wrow[i4]);
#pragma unroll
            for (int r = 0; r < 16; r++) {
                ulonglong2 f = *(const ulonglong2*)&F_s[r][i4 * 4];
                fma2(acc[r], wv.x, f.x);
                fma2(acc[r], wv.y, f.y);
            }
        }
        float* dst = wfa + (size_t)cn * 768 + (size_t)k * 16;
#pragma unroll
        for (int r = 0; r < 16; r += 4)
            *(float4*)(dst + r) = make_float4(fold2(acc[r]), fold2(acc[r+1]),
                                              fold2(acc[r+2]), fold2(acc[r+3]));
    } else {
        const int r = tid - 48;
        u64 acc[16];
#pragma unroll
        for (int r4 = 0; r4 < 16; r4++) acc[r4] = 0ull;
#pragma unroll 4
        for (int i4 = 0; i4 < 16; i4++) {
            ulonglong2 av = *(const ulonglong2*)&fi5s[r][i4 * 4];
#pragma unroll
            for (int r4 = 0; r4 < 16; r4++) {
                ulonglong2 f = *(const ulonglong2*)&F_s[r4][i4 * 4];
                fma2(acc[r4], av.x, f.x);
                fma2(acc[r4], av.y, f.y);
            }
        }
        float* dst = gg + (size_t)cn * 256 + (size_t)r * 16;
#pragma unroll
        for (int r4 = 0; r4 < 16; r4 += 4)
            *(float4*)(dst + r4) = make_float4(fold2(acc[r4]), fold2(acc[r4+1]),
                                               fold2(acc[r4+2]), fold2(acc[r4+3]));
    }
}

// ---------------------------------------------------------------------------
// Levels 0+1 fused. 32 blocks x 64.
// ---------------------------------------------------------------------------
__global__ __launch_bounds__(64)
void qt_l01(const float* __restrict__ x0, float4* __restrict__ xout,
            const float* __restrict__ fin,
            const float* __restrict__ ftl, const float* __restrict__ ftr,
            const float* __restrict__ fbl, const float* __restrict__ fbr,
            const float* __restrict__ scale)
{
    __shared__ __align__(16) float fiA[16][64], FA[16][64], fiB[16][64], FB[16][64];
    __shared__ float4 x_s[16][64];

    const int bid = blockIdx.x;
    const int p1  = bid >> 3;
    const int c1  = (bid >> 1) & 3;
    const int qh  = bid & 1;
    const int tid = threadIdx.x;

    const float* FcA = (p1 == 0 ? ftl : p1 == 1 ? ftr : p1 == 2 ? fbl : fbr);
    const int nodeB = 1 + p1;
    const float* FcB = (c1 == 0 ? ftl : c1 == 1 ? ftr : c1 == 2 ? fbl : fbr)
                       + (size_t)nodeB * 1024;

    stage_factor_n(fiA, fin, scale, tid, 64);
    stage_factor_n(FA,  FcA, nullptr, tid, 64);
    stage_factor_n(fiB, fin + (size_t)nodeB * 1024, scale + (size_t)nodeB * 16, tid, 64);
    stage_factor_n(FB,  FcB, nullptr, tid, 64);
    {
        const int b = qh * 64 + tid;
        const float4* xp = (const float4*)(x0 + (size_t)b * 64);
#pragma unroll
        for (int i4 = 0; i4 < 16; i4++)
            x_s[i4][tid] = xp[i4];
    }
    __syncthreads();

    float lat[16]; u64 lp[16];
    lat_from_smem(lat, fiA, x_s, tid);
    duppack16(lp, lat);
    update_smem(x_s, FA, lp, tid);
    lat_from_smem(lat, fiB, x_s, tid);
    duppack16(lp, lat);

    const int gr = p1 >> 1, gc = p1 & 1;
    const int cn = (2 * gr + (c1 >> 1)) * 4 + 2 * gc + (c1 & 1);
    float4* op = xout + ((size_t)cn * 16) * 128 + qh * 64 + tid;
    emit_global(op, x_s, FB, lp, tid);
}

// ---------------------------------------------------------------------------
// Levels 2+3 fused. 512 blocks x 64.
// ---------------------------------------------------------------------------
__global__ __launch_bounds__(64)
void qt_l23(const float4* __restrict__ xin, float4* __restrict__ xout,
            const float* __restrict__ fin,
            const float* __restrict__ ftl, const float* __restrict__ ftr,
            const float* __restrict__ fbl, const float* __restrict__ fbr,
            const float* __restrict__ scale)
{
    __shared__ __align__(16) float fiA[16][64], FA[16][64], fiB[16][64], FB[16][64];
    __shared__ float4 x_s[16][64];

    const int bid = blockIdx.x;
    const int p3  = bid >> 3;
    const int c3  = (bid >> 1) & 3;
    const int qh  = bid & 1;
    const int tid = threadIdx.x;

    const int r3 = p3 >> 3, k3 = p3 & 7;
    const int p2 = (r3 >> 1) * 4 + (k3 >> 1);
    const int c2 = ((r3 & 1) << 1) | (k3 & 1);

    const int nodeA = 5 + p2;
    const int nodeB = 21 + p3;
    const float* FcA = (c2 == 0 ? ftl : c2 == 1 ? ftr : c2 == 2 ? fbl : fbr)
                       + (size_t)nodeA * 1024;
    const float* FcB = (c3 == 0 ? ftl : c3 == 1 ? ftr : c3 == 2 ? fbl : fbr)
                       + (size_t)nodeB * 1024;

    stage_factor_n(fiA, fin + (size_t)nodeA * 1024, scale + (size_t)nodeA * 16, tid, 64);
    stage_factor_n(FA,  FcA, nullptr, tid, 64);
    stage_factor_n(fiB, fin + (size_t)nodeB * 1024, scale + (size_t)nodeB * 16, tid, 64);
    stage_factor_n(FB,  FcB, nullptr, tid, 64);
    {
        const float4* xp = xin + ((size_t)p2 * 16) * 128 + qh * 64 + tid;
#pragma unroll
        for (int i4 = 0; i4 < 16; i4++)
            x_s[i4][tid] = xp[i4 * 128];
    }
    __syncthreads();

    float lat[16]; u64 lp[16];
    lat_from_smem(lat, fiA, x_s, tid);
    duppack16(lp, lat);
    update_smem(x_s, FA, lp, tid);
    lat_from_smem(lat, fiB, x_s, tid);
    duppack16(lp, lat);

    const int gr = p3 >> 3, gc = p3 & 7;
    const int cn = (2 * gr + (c3 >> 1)) * 16 + 2 * gc + (c3 & 1);
    float4* op = xout + ((size_t)cn * 16) * 128 + qh * 64 + tid;
    emit_global(op, x_s, FB, lp, tid);
}

// ---------------------------------------------------------------------------
// qt_stack: per (p4, q4) compute stacked GEMV: [fi4s | fi5s(cn0..3) | W] . x4
//   rows 0..15  -> LAT4[p4][r][b]
//   rows 16+16j -> F5X[cn_j][r][b]
//   rows 80..127-> WX[p4][k][b] (+head_b)
// grid = 1024 (p4*4+q4), 128 thr = rq(4) x col(32). 2 halves of 16 rows each.
// ---------------------------------------------------------------------------
__global__ __launch_bounds__(128, 4)
void qt_stack(const float4* __restrict__ xin,
              const float* __restrict__ fin, const float* __restrict__ scale,
              const float* __restrict__ head_w, const float* __restrict__ head_b,
              float* __restrict__ lat4o, float* __restrict__ f5xo,
              float* __restrict__ wxo)
{
    __shared__ __align__(16) float FI[128][64];
    __shared__ __align__(16) float4 x_s[16][32];
    __shared__ float hb_s[48];

    const int bid = blockIdx.x;
    const int p4  = bid >> 2;
    const int q4  = bid & 3;
    const int tid = threadIdx.x;
    const int col = tid & 31;
    const int rq  = tid >> 5;

    const int gr4 = p4 >> 4, gc4 = p4 & 15;
    const int nodeA = 85 + p4;

    // rows 0..15: fi4s
    stage_factor_n((float (*)[64])&FI[0], fin + (size_t)nodeA * 1024,
                   scale + (size_t)nodeA * 16, tid, 128);
    // rows 16+16j: fi5s of child j
#pragma unroll
    for (int j = 0; j < 4; j++) {
        const int cnj = (2 * gr4 + (j >> 1)) * 32 + 2 * gc4 + (j & 1);
        const int node = 341 + cnj;
        stage_factor_n((float (*)[64])&FI[16 + 16 * j], fin + (size_t)node * 1024,
                       scale + (size_t)node * 16, tid, 128);
    }
    // rows 80..127: head_w
    {
        const float4* w4 = (const float4*)head_w;
        float4* d = (float4*)&FI[80][0];
        for (int i = tid; i < 768; i += 128) d[i] = w4[i];
        if (tid < 48) hb_s[tid] = head_b[tid];
        const float4* xbase = xin + (size_t)p4 * 16 * 128 + q4 * 32;
#pragma unroll
        for (int j = 0; j < 4; j++) {
            int idx = tid + j * 128;
            x_s[idx >> 5][idx & 31] = xbase[(idx >> 5) * 128 + (idx & 31)];
        }
    }
    __syncthreads();

    const int b = q4 * 32 + col;

#pragma unroll 1
    for (int half = 0; half < 2; half++) {
        const int g = rq * 2 + half;       // row group 0..7 (warp-uniform)
        const int rbase = g * 16;

        u64 acc[16];
#pragma unroll
        for (int rr = 0; rr < 16; rr++) acc[rr] = 0ull;
#pragma unroll 2
        for (int i4 = 0; i4 < 16; i4++) {
            ulonglong2 xv = *(const ulonglong2*)&x_s[i4][col];
#pragma unroll
            for (int rr = 0; rr < 16; rr++) {
                ulonglong2 f = *(const ulonglong2*)&FI[rbase + rr][i4 * 4];
                fma2(acc[rr], xv.x, f.x);
                fma2(acc[rr], xv.y, f.y);
            }
        }

        if (g == 0) {
            float* dst = lat4o + (size_t)p4 * 16 * 128 + b;
#pragma unroll
            for (int rr = 0; rr < 16; rr++) dst[rr * 128] = fold2(acc[rr]);
        } else if (g <= 4) {
            const int j = g - 1;
            const int cnj = (2 * gr4 + (j >> 1)) * 32 + 2 * gc4 + (j & 1);
            float* dst = f5xo + (size_t)cnj * 16 * 128 + b;
#pragma unroll
            for (int rr = 0; rr < 16; rr++) dst[rr * 128] = fold2(acc[rr]);
        } else {
            const int k0 = (g - 5) * 16;
            float* dst = wxo + ((size_t)p4 * 48 + k0) * 128 + b;
#pragma unroll
            for (int rr = 0; rr < 16; rr++)
                dst[rr * 128] = fold2(acc[rr]) + hb_s[k0 + rr];
        }
    }
}

// ---------------------------------------------------------------------------
// qt_final: pure lat-space. grid = 4096 (cn*4+q4), 128 thr = kq(4) x col(32).
//   lat5 = F5X[cn] + G[cn].lat4 ; tk = WX + WFA[cn].lat4 ;
//   per c: y = tk + WF5[cn][c].lat5 -> pixels (pr == kq).
// ---------------------------------------------------------------------------
__global__ __launch_bounds__(128, 6)
void qt_final(const float* __restrict__ lat4i, const float* __restrict__ f5xi,
              const float* __restrict__ wxi,
              const float* __restrict__ wf, const float* __restrict__ wfa,
              const float* __restrict__ gg,
              float* __restrict__ out)
{
    __shared__ __align__(16) float g_s[16][16];
    __shared__ __align__(16) float wfa_s[48][16];
    __shared__ __align__(16) float wf5_s[4 * 48][16];

    const int bid = blockIdx.x;
    const int cn  = bid >> 2;
    const int q4  = bid & 3;
    const int tid = threadIdx.x;
    const int col = tid & 31;
    const int kq  = tid >> 5;
    const int k0  = kq * 12;

    const int r5 = cn >> 5, c5 = cn & 31;
    const int p4 = (r5 >> 1) * 16 + (c5 >> 1);
    const int b  = q4 * 32 + col;

    {
        if (tid < 64)
            ((float4*)g_s)[tid] = ((const float4*)(gg + (size_t)cn * 256))[tid];
        const float4* sa = (const float4*)(wfa + (size_t)cn * 768);
        float4* da = (float4*)wfa_s;
        for (int i = tid; i < 192; i += 128) da[i] = sa[i];
        const float4* s5 = (const float4*)(wf + (size_t)cn * 3072);
        float4* d5 = (float4*)wf5_s;
        for (int i = tid; i < 768; i += 128) d5[i] = s5[i];
    }

    // lat4 of parent (coalesced per-warp LDG)
    float l4[16];
    {
        const float* lp = lat4i + (size_t)p4 * 16 * 128 + b;
#pragma unroll
        for (int r = 0; r < 16; r++) l4[r] = __ldg(&lp[r * 128]);
    }
    u64 latq4[8];
#pragma unroll
    for (int j = 0; j < 8; j++) latq4[j] = pack2(l4[2*j], l4[2*j + 1]);

    __syncthreads();

    // lat5 = F5X + G.lat4
    float l5[16];
    {
        const float* fp = f5xi + (size_t)cn * 16 * 128 + b;
#pragma unroll
        for (int r = 0; r < 16; r++) {
            const ulonglong2* grow = (const ulonglong2*)&g_s[r][0];
            u64 a = 0ull;
#pragma unroll
            for (int j = 0; j < 4; j++) {
                ulonglong2 f = grow[j];
                fma2(a, latq4[2*j],     f.x);
                fma2(a, latq4[2*j + 1], f.y);
            }
            l5[r] = __ldg(&fp[r * 128]) + fold2(a);
        }
    }
    u64 latq5[8];
#pragma unroll
    for (int j = 0; j < 8; j++) latq5[j] = pack2(l5[2*j], l5[2*j + 1]);

    // tk = WX + WFA.lat4 (own 12 k's)
    float tk[12];
    {
        const float* wxp = wxi + ((size_t)p4 * 48 + k0) * 128 + b;
#pragma unroll
        for (int kk = 0; kk < 12; kk++) {
            const ulonglong2* ar = (const ulonglong2*)&wfa_s[k0 + kk][0];
            u64 a = 0ull;
#pragma unroll
            for (int j = 0; j < 4; j++) {
                ulonglong2 f = ar[j];
                fma2(a, latq4[2*j],     f.x);
                fma2(a, latq4[2*j + 1], f.y);
            }
            tk[kk] = __ldg(&wxp[kk * 128]) + fold2(a);
        }
    }

    // 4 children -> pixels
#pragma unroll 1
    for (int c = 0; c < 4; c++) {
        const int cn6 = (2 * r5 + (c >> 1)) * 64 + 2 * c5 + (c & 1);

        float acc[12];
#pragma unroll
        for (int kk = 0; kk < 12; kk++) {
            const ulonglong2* wfr = (const ulonglong2*)&wf5_s[c * 48 + k0 + kk][0];
            u64 a = 0ull;
#pragma unroll
            for (int j = 0; j < 4; j++) {
                ulonglong2 f = wfr[j];
                fma2(a, latq5[2*j],     f.x);
                fma2(a, latq5[2*j + 1], f.y);
            }
            acc[kk] = tk[kk] + fold2(a);
        }

        // k = kq*12 + pc*3 + oc  ->  pr == kq
        const int sr = cn6 >> 6, sc = cn6 & 63;
#pragma unroll
        for (int oc = 0; oc < 3; oc++) {
            float4 v = make_float4(acc[0 + oc], acc[3 + oc], acc[6 + oc], acc[9 + oc]);
            size_t row = (size_t)(b * 3 + oc) * 256 + (sr * 4 + kq);
            *(float4*)(out + row * 256 + sc * 4) = v;
        }
    }
}

// ---------------------------------------------------------------------------
extern "C" void kernel_launch(void* const* d_in, const int* in_sizes, int n_in,
                              void* d_out, int out_size)
{
    const float* x      = (const float*)d_in[0];
    const float* fin    = (const float*)d_in[1];
    const float* ftl    = (const float*)d_in[2];
    const float* ftr    = (const float*)d_in[3];
    const float* fbl    = (const float*)d_in[4];
    const float* fbr    = (const float*)d_in[5];
    const float* scale  = (const float*)d_in[6];
    const float* head_w = (const float*)d_in[7];
    const float* head_b = (const float*)d_in[8];
    float* out = (float*)d_out;

    float4 *x2, *x4;
    float  *wfb, *wfab, *ggb, *lat4b, *f5xb, *wxb;
    cudaGetSymbolAddress((void**)&x2,    g_x2);
    cudaGetSymbolAddress((void**)&x4,    g_x4);
    cudaGetSymbolAddress((void**)&wfb,   g_wf);
    cudaGetSymbolAddress((void**)&wfab,  g_wfa);
    cudaGetSymbolAddress((void**)&ggb,   g_g);
    cudaGetSymbolAddress((void**)&lat4b, g_lat4);
    cudaGetSymbolAddress((void**)&f5xb,  g_f5x);
    cudaGetSymbolAddress((void**)&wxb,   g_wx);

    qt_wf_kernel<<<4096, 64>>>(ftl, ftr, fbl, fbr, head_w, wfb);
    qt_wfa_g_kernel<<<1024, 64>>>(ftl, ftr, fbl, fbr, fin, scale, head_w, wfab, ggb);
    qt_l01<<<32,  64>>>(x,  x2, fin, ftl, ftr, fbl, fbr, scale);
    qt_l23<<<512, 64>>>(x2, x4, fin, ftl, ftr, fbl, fbr, scale);
    qt_stack<<<1024, 128>>>(x4, fin, scale, head_w, head_b, lat4b, f5xb, wxb);
    qt_final<<<4096, 128>>>(lat4b, f5xb, wxb, wfb, wfab, ggb, out);
}

// round 13
// speedup vs baseline: 1.0531x; 1.0531x over previous
#include <cuda_runtime.h>
#include <cstdint>

// ---------------------------------------------------------------------------
// QuadTreeDecoder round 13
//  - qt_prep: single prep kernel (WF5 + WFA + G), 1024 blocks x 256
//  - qt_l01 / qt_l23: 128-thr oh-split (lat halves via lat_s, o-half update)
//  - qt_stack / qt_final: unchanged from R12 (validated)
// ---------------------------------------------------------------------------

typedef unsigned long long u64;

__device__ float4 g_x2[(size_t)16  * 16 * 128];
__device__ float4 g_x4[(size_t)256 * 16 * 128];
__device__ float  g_wf[(size_t)1024 * 4 * 48 * 16];   // WF5[cn][c][48][16]
__device__ float  g_wfa[(size_t)1024 * 48 * 16];      // WFA[cn][48][16]
__device__ float  g_g[(size_t)1024 * 16 * 16];        // G[cn][16][16]
__device__ float  g_lat4[(size_t)256 * 16 * 128];     // LAT4[p4][r][b]
__device__ float  g_f5x[(size_t)1024 * 16 * 128];     // F5X[cn][r][b]
__device__ float  g_wx[(size_t)256 * 48 * 128];       // WX[p4][k][b]

// ---------------------------------------------------------------------------
__device__ __forceinline__ void fma2(u64& d, u64 a, u64 b) {
    asm("fma.rn.f32x2 %0, %1, %2, %3;" : "=l"(d) : "l"(a), "l"(b), "l"(d));
}
__device__ __forceinline__ u64 pack2(float lo, float hi) {
    u64 r; asm("mov.b64 %0, {%1, %2};" : "=l"(r) : "f"(lo), "f"(hi)); return r;
}
__device__ __forceinline__ float fold2(u64 v) {
    float lo, hi; asm("mov.b64 {%0, %1}, %2;" : "=f"(lo), "=f"(hi) : "l"(v));
    return lo + hi;
}

// ---------------------------------------------------------------------------
__device__ __forceinline__ void stage_factor_n(float dst[16][64], const float* __restrict__ src,
                                               const float* __restrict__ sc, int tid, int nthr)
{
    const float4* s4 = (const float4*)src;
    float4* d4 = (float4*)dst;
    if (sc) {
        for (int idx = tid; idx < 256; idx += nthr) {
            float4 v = s4[idx];
            float s = __ldg(&sc[idx >> 4]);
            v.x *= s; v.y *= s; v.z *= s; v.w *= s;
            d4[idx] = v;
        }
    } else {
        for (int idx = tid; idx < 256; idx += nthr)
            d4[idx] = s4[idx];
    }
}

// ---------------------------------------------------------------------------
// qt_prep: per cn (1024 blocks x 256):
//   WF5[cn][c][k][r] = W[k]   . F5_c[341+cn][r]   (threads 0..191)
//   WFA[cn][k][r4]   = W[k]   . F4_c4[85+p4][r4]  (threads 192..239)
//   G  [cn][r][r4]   = fi5s[r]. F4_c4[85+p4][r4]  (threads 240..255)
// ---------------------------------------------------------------------------
__global__ __launch_bounds__(256)
void qt_prep(const float* __restrict__ ftl, const float* __restrict__ ftr,
             const float* __restrict__ fbl, const float* __restrict__ fbr,
             const float* __restrict__ fin, const float* __restrict__ scale,
             const float* __restrict__ head_w,
             float* __restrict__ wf, float* __restrict__ wfa, float* __restrict__ gg)
{
    __shared__ __align__(16) float F4s[16][64];
    __shared__ __align__(16) float fi5s[16][64];
    __shared__ __align__(16) float F5s[4][16][64];
    __shared__ __align__(16) float w_s[48][64];

    const int cn  = blockIdx.x;
    const int tid = threadIdx.x;
    const int r5 = cn >> 5, c5 = cn & 31;
    const int p4 = (r5 >> 1) * 16 + (c5 >> 1);
    const int c4 = ((r5 & 1) << 1) | (c5 & 1);
    const int nodeA = 85 + p4;
    const int nodeB = 341 + cn;

    const float* FcA = (c4 == 0 ? ftl : c4 == 1 ? ftr : c4 == 2 ? fbl : fbr)
                       + (size_t)nodeA * 1024;

    stage_factor_n(F4s, FcA, nullptr, tid, 256);
    stage_factor_n(fi5s, fin + (size_t)nodeB * 1024, scale + (size_t)nodeB * 16, tid, 256);
    stage_factor_n(F5s[0], ftl + (size_t)nodeB * 1024, nullptr, tid, 256);
    stage_factor_n(F5s[1], ftr + (size_t)nodeB * 1024, nullptr, tid, 256);
    stage_factor_n(F5s[2], fbl + (size_t)nodeB * 1024, nullptr, tid, 256);
    stage_factor_n(F5s[3], fbr + (size_t)nodeB * 1024, nullptr, tid, 256);
    {
        const float4* w4 = (const float4*)head_w;
        float4* d = (float4*)w_s;
        for (int i = tid; i < 768; i += 256) d[i] = w4[i];
    }
    __syncthreads();

    u64 acc[16];
#pragma unroll
    for (int r = 0; r < 16; r++) acc[r] = 0ull;

    if (tid < 192) {
        const int c = tid / 48;
        const int k = tid - c * 48;
#pragma unroll 4
        for (int i4 = 0; i4 < 16; i4++) {
            ulonglong2 wv = *(const ulonglong2*)&w_s[k][i4 * 4];
#pragma unroll
            for (int r = 0; r < 16; r++) {
                ulonglong2 f = *(const ulonglong2*)&F5s[c][r][i4 * 4];
                fma2(acc[r], wv.x, f.x);
                fma2(acc[r], wv.y, f.y);
            }
        }
        float* dst = wf + ((size_t)cn * 4 + c) * 768 + (size_t)k * 16;
#pragma unroll
        for (int r = 0; r < 16; r += 4)
            *(float4*)(dst + r) = make_float4(fold2(acc[r]), fold2(acc[r+1]),
                                              fold2(acc[r+2]), fold2(acc[r+3]));
    } else if (tid < 240) {
        const int k = tid - 192;
#pragma unroll 4
        for (int i4 = 0; i4 < 16; i4++) {
            ulonglong2 wv = *(const ulonglong2*)&w_s[k][i4 * 4];
#pragma unroll
            for (int r = 0; r < 16; r++) {
                ulonglong2 f = *(const ulonglong2*)&F4s[r][i4 * 4];
                fma2(acc[r], wv.x, f.x);
                fma2(acc[r], wv.y, f.y);
            }
        }
        float* dst = wfa + (size_t)cn * 768 + (size_t)k * 16;
#pragma unroll
        for (int r = 0; r < 16; r += 4)
            *(float4*)(dst + r) = make_float4(fold2(acc[r]), fold2(acc[r+1]),
                                              fold2(acc[r+2]), fold2(acc[r+3]));
    } else {
        const int r = tid - 240;
#pragma unroll 4
        for (int i4 = 0; i4 < 16; i4++) {
            ulonglong2 av = *(const ulonglong2*)&fi5s[r][i4 * 4];
#pragma unroll
            for (int r4 = 0; r4 < 16; r4++) {
                ulonglong2 f = *(const ulonglong2*)&F4s[r4][i4 * 4];
                fma2(acc[r4], av.x, f.x);
                fma2(acc[r4], av.y, f.y);
            }
        }
        float* dst = gg + (size_t)cn * 256 + (size_t)r * 16;
#pragma unroll
        for (int r4 = 0; r4 < 16; r4 += 4)
            *(float4*)(dst + r4) = make_float4(fold2(acc[r4]), fold2(acc[r4+1]),
                                               fold2(acc[r4+2]), fold2(acc[r4+3]));
    }
}

// ---------------------------------------------------------------------------
// Levels 0+1 fused, oh-split. bid = (p1*4 + c1)*2 + qh, 32 blocks x 128.
// threads = oh(2) x col(64).
// ---------------------------------------------------------------------------
__global__ __launch_bounds__(128)
void qt_l01(const float* __restrict__ x0, float4* __restrict__ xout,
            const float* __restrict__ fin,
            const float* __restrict__ ftl, const float* __restrict__ ftr,
            const float* __restrict__ fbl, const float* __restrict__ fbr,
            const float* __restrict__ scale)
{
    __shared__ __align__(16) float fiA[16][64], FA[16][64], fiB[16][64], FB[16][64];
    __shared__ __align__(16) float4 x_s[16][64];
    __shared__ float lat_s[16][64];

    const int bid = blockIdx.x;
    const int p1  = bid >> 3;
    const int c1  = (bid >> 1) & 3;
    const int qh  = bid & 1;
    const int tid = threadIdx.x;
    const int col = tid & 63;
    const int oh  = tid >> 6;
    const int rb  = oh * 8;

    const float* FcA = (p1 == 0 ? ftl : p1 == 1 ? ftr : p1 == 2 ? fbl : fbr);
    const int nodeB = 1 + p1;
    const float* FcB = (c1 == 0 ? ftl : c1 == 1 ? ftr : c1 == 2 ? fbl : fbr)
                       + (size_t)nodeB * 1024;

    stage_factor_n(fiA, fin, scale, tid, 128);
    stage_factor_n(FA,  FcA, nullptr, tid, 128);
    stage_factor_n(fiB, fin + (size_t)nodeB * 1024, scale + (size_t)nodeB * 16, tid, 128);
    stage_factor_n(FB,  FcB, nullptr, tid, 128);
    {
        // x0 b-major: 1024 float4, 8 per thread
#pragma unroll
        for (int j = 0; j < 8; j++) {
            int idx = tid + j * 128;               // i4*64 + c
            int i4 = idx >> 6, c = idx & 63;
            x_s[i4][c] = ((const float4*)(x0 + (size_t)(qh * 64 + c) * 64))[i4];
        }
    }
    __syncthreads();

    u64 lp[16];

    // P1: latA r-half
    {
        u64 a[8];
#pragma unroll
        for (int rr = 0; rr < 8; rr++) a[rr] = 0ull;
#pragma unroll 4
        for (int i4 = 0; i4 < 16; i4++) {
            ulonglong2 xv = *(const ulonglong2*)&x_s[i4][col];
#pragma unroll
            for (int rr = 0; rr < 8; rr++) {
                ulonglong2 f = *(const ulonglong2*)&fiA[rb + rr][i4 * 4];
                fma2(a[rr], xv.x, f.x);
                fma2(a[rr], xv.y, f.y);
            }
        }
#pragma unroll
        for (int rr = 0; rr < 8; rr++) lat_s[rb + rr][col] = fold2(a[rr]);
    }
    __syncthreads();

    // P2: update o-half
#pragma unroll
    for (int r = 0; r < 16; r++) { float v = lat_s[r][col]; lp[r] = pack2(v, v); }
#pragma unroll 4
    for (int oo = 0; oo < 8; oo++) {
        const int o4 = rb + oo;
        ulonglong2 a = *(const ulonglong2*)&x_s[o4][col];
#pragma unroll
        for (int r = 0; r < 16; r++) {
            ulonglong2 f = *(const ulonglong2*)&FA[r][o4 * 4];
            fma2(a.x, lp[r], f.x);
            fma2(a.y, lp[r], f.y);
        }
        *(ulonglong2*)&x_s[o4][col] = a;
    }
    __syncthreads();

    // P3: latB r-half
    {
        u64 a[8];
#pragma unroll
        for (int rr = 0; rr < 8; rr++) a[rr] = 0ull;
#pragma unroll 4
        for (int i4 = 0; i4 < 16; i4++) {
            ulonglong2 xv = *(const ulonglong2*)&x_s[i4][col];
#pragma unroll
            for (int rr = 0; rr < 8; rr++) {
                ulonglong2 f = *(const ulonglong2*)&fiB[rb + rr][i4 * 4];
                fma2(a[rr], xv.x, f.x);
                fma2(a[rr], xv.y, f.y);
            }
        }
#pragma unroll
        for (int rr = 0; rr < 8; rr++) lat_s[rb + rr][col] = fold2(a[rr]);
    }
    __syncthreads();

    // P4: emit o-half
#pragma unroll
    for (int r = 0; r < 16; r++) { float v = lat_s[r][col]; lp[r] = pack2(v, v); }
    const int gr = p1 >> 1, gc = p1 & 1;
    const int cn = (2 * gr + (c1 >> 1)) * 4 + 2 * gc + (c1 & 1);
    float4* op = xout + ((size_t)cn * 16) * 128 + qh * 64 + col;
#pragma unroll 4
    for (int oo = 0; oo < 8; oo++) {
        const int o4 = rb + oo;
        ulonglong2 a = *(const ulonglong2*)&x_s[o4][col];
#pragma unroll
        for (int r = 0; r < 16; r++) {
            ulonglong2 f = *(const ulonglong2*)&FB[r][o4 * 4];
            fma2(a.x, lp[r], f.x);
            fma2(a.y, lp[r], f.y);
        }
        *(ulonglong2*)&op[o4 * 128] = a;
    }
}

// ---------------------------------------------------------------------------
// Levels 2+3 fused, oh-split. bid = (p3*4 + c3)*2 + qh, 512 blocks x 128.
// ---------------------------------------------------------------------------
__global__ __launch_bounds__(128)
void qt_l23(const float4* __restrict__ xin, float4* __restrict__ xout,
            const float* __restrict__ fin,
            const float* __restrict__ ftl, const float* __restrict__ ftr,
            const float* __restrict__ fbl, const float* __restrict__ fbr,
            const float* __restrict__ scale)
{
    __shared__ __align__(16) float fiA[16][64], FA[16][64], fiB[16][64], FB[16][64];
    __shared__ __align__(16) float4 x_s[16][64];
    __shared__ float lat_s[16][64];

    const int bid = blockIdx.x;
    const int p3  = bid >> 3;
    const int c3  = (bid >> 1) & 3;
    const int qh  = bid & 1;
    const int tid = threadIdx.x;
    const int col = tid & 63;
    const int oh  = tid >> 6;
    const int rb  = oh * 8;

    const int r3 = p3 >> 3, k3 = p3 & 7;
    const int p2 = (r3 >> 1) * 4 + (k3 >> 1);
    const int c2 = ((r3 & 1) << 1) | (k3 & 1);

    const int nodeA = 5 + p2;
    const int nodeB = 21 + p3;
    const float* FcA = (c2 == 0 ? ftl : c2 == 1 ? ftr : c2 == 2 ? fbl : fbr)
                       + (size_t)nodeA * 1024;
    const float* FcB = (c3 == 0 ? ftl : c3 == 1 ? ftr : c3 == 2 ? fbl : fbr)
                       + (size_t)nodeB * 1024;

    stage_factor_n(fiA, fin + (size_t)nodeA * 1024, scale + (size_t)nodeA * 16, tid, 128);
    stage_factor_n(FA,  FcA, nullptr, tid, 128);
    stage_factor_n(fiB, fin + (size_t)nodeB * 1024, scale + (size_t)nodeB * 16, tid, 128);
    stage_factor_n(FB,  FcB, nullptr, tid, 128);
    {
        const float4* xbase = xin + (size_t)p2 * 16 * 128 + qh * 64;
#pragma unroll
        for (int j = 0; j < 8; j++) {
            int idx = tid + j * 128;               // i4*64 + c
            x_s[idx >> 6][idx & 63] = xbase[(idx >> 6) * 128 + (idx & 63)];
        }
    }
    __syncthreads();

    u64 lp[16];

    // P1: latA r-half
    {
        u64 a[8];
#pragma unroll
        for (int rr = 0; rr < 8; rr++) a[rr] = 0ull;
#pragma unroll 4
        for (int i4 = 0; i4 < 16; i4++) {
            ulonglong2 xv = *(const ulonglong2*)&x_s[i4][col];
#pragma unroll
            for (int rr = 0; rr < 8; rr++) {
                ulonglong2 f = *(const ulonglong2*)&fiA[rb + rr][i4 * 4];
                fma2(a[rr], xv.x, f.x);
                fma2(a[rr], xv.y, f.y);
            }
        }
#pragma unroll
        for (int rr = 0; rr < 8; rr++) lat_s[rb + rr][col] = fold2(a[rr]);
    }
    __syncthreads();

    // P2: update o-half
#pragma unroll
    for (int r = 0; r < 16; r++) { float v = lat_s[r][col]; lp[r] = pack2(v, v); }
#pragma unroll 4
    for (int oo = 0; oo < 8; oo++) {
        const int o4 = rb + oo;
        ulonglong2 a = *(const ulonglong2*)&x_s[o4][col];
#pragma unroll
        for (int r = 0; r < 16; r++) {
            ulonglong2 f = *(const ulonglong2*)&FA[r][o4 * 4];
            fma2(a.x, lp[r], f.x);
            fma2(a.y, lp[r], f.y);
        }
        *(ulonglong2*)&x_s[o4][col] = a;
    }
    __syncthreads();

    // P3: latB r-half
    {
        u64 a[8];
#pragma unroll
        for (int rr = 0; rr < 8; rr++) a[rr] = 0ull;
#pragma unroll 4
        for (int i4 = 0; i4 < 16; i4++) {
            ulonglong2 xv = *(const ulonglong2*)&x_s[i4][col];
#pragma unroll
            for (int rr = 0; rr < 8; rr++) {
                ulonglong2 f = *(const ulonglong2*)&fiB[rb + rr][i4 * 4];
                fma2(a[rr], xv.x, f.x);
                fma2(a[rr], xv.y, f.y);
            }
        }
#pragma unroll
        for (int rr = 0; rr < 8; rr++) lat_s[rb + rr][col] = fold2(a[rr]);
    }
    __syncthreads();

    // P4: emit o-half
#pragma unroll
    for (int r = 0; r < 16; r++) { float v = lat_s[r][col]; lp[r] = pack2(v, v); }
    const int gr = p3 >> 3, gc = p3 & 7;
    const int cn = (2 * gr + (c3 >> 1)) * 16 + 2 * gc + (c3 & 1);
    float4* op = xout + ((size_t)cn * 16) * 128 + qh * 64 + col;
#pragma unroll 4
    for (int oo = 0; oo < 8; oo++) {
        const int o4 = rb + oo;
        ulonglong2 a = *(const ulonglong2*)&x_s[o4][col];
#pragma unroll
        for (int r = 0; r < 16; r++) {
            ulonglong2 f = *(const ulonglong2*)&FB[r][o4 * 4];
            fma2(a.x, lp[r], f.x);
            fma2(a.y, lp[r], f.y);
        }
        *(ulonglong2*)&op[o4 * 128] = a;
    }
}

// ---------------------------------------------------------------------------
// qt_stack: per (p4, q4) stacked GEMV [fi4s | fi5s(cn0..3) | W] . x4
// grid = 1024, 128 thr = rq(4) x col(32), 2 halves of 16 rows.
// ---------------------------------------------------------------------------
__global__ __launch_bounds__(128, 4)
void qt_stack(const float4* __restrict__ xin,
              const float* __restrict__ fin, const float* __restrict__ scale,
              const float* __restrict__ head_w, const float* __restrict__ head_b,
              float* __restrict__ lat4o, float* __restrict__ f5xo,
              float* __restrict__ wxo)
{
    __shared__ __align__(16) float FI[128][64];
    __shared__ __align__(16) float4 x_s[16][32];
    __shared__ float hb_s[48];

    const int bid = blockIdx.x;
    const int p4  = bid >> 2;
    const int q4  = bid & 3;
    const int tid = threadIdx.x;
    const int col = tid & 31;
    const int rq  = tid >> 5;

    const int gr4 = p4 >> 4, gc4 = p4 & 15;
    const int nodeA = 85 + p4;

    stage_factor_n((float (*)[64])&FI[0], fin + (size_t)nodeA * 1024,
                   scale + (size_t)nodeA * 16, tid, 128);
#pragma unroll
    for (int j = 0; j < 4; j++) {
        const int cnj = (2 * gr4 + (j >> 1)) * 32 + 2 * gc4 + (j & 1);
        const int node = 341 + cnj;
        stage_factor_n((float (*)[64])&FI[16 + 16 * j], fin + (size_t)node * 1024,
                       scale + (size_t)node * 16, tid, 128);
    }
    {
        const float4* w4 = (const float4*)head_w;
        float4* d = (float4*)&FI[80][0];
        for (int i = tid; i < 768; i += 128) d[i] = w4[i];
        if (tid < 48) hb_s[tid] = head_b[tid];
        const float4* xbase = xin + (size_t)p4 * 16 * 128 + q4 * 32;
#pragma unroll
        for (int j = 0; j < 4; j++) {
            int idx = tid + j * 128;
            x_s[idx >> 5][idx & 31] = xbase[(idx >> 5) * 128 + (idx & 31)];
        }
    }
    __syncthreads();

    const int b = q4 * 32 + col;

#pragma unroll 1
    for (int half = 0; half < 2; half++) {
        const int g = rq * 2 + half;
        const int rbase = g * 16;

        u64 acc[16];
#pragma unroll
        for (int rr = 0; rr < 16; rr++) acc[rr] = 0ull;
#pragma unroll 2
        for (int i4 = 0; i4 < 16; i4++) {
            ulonglong2 xv = *(const ulonglong2*)&x_s[i4][col];
#pragma unroll
            for (int rr = 0; rr < 16; rr++) {
                ulonglong2 f = *(const ulonglong2*)&FI[rbase + rr][i4 * 4];
                fma2(acc[rr], xv.x, f.x);
                fma2(acc[rr], xv.y, f.y);
            }
        }

        if (g == 0) {
            float* dst = lat4o + (size_t)p4 * 16 * 128 + b;
#pragma unroll
            for (int rr = 0; rr < 16; rr++) dst[rr * 128] = fold2(acc[rr]);
        } else if (g <= 4) {
            const int j = g - 1;
            const int cnj = (2 * gr4 + (j >> 1)) * 32 + 2 * gc4 + (j & 1);
            float* dst = f5xo + (size_t)cnj * 16 * 128 + b;
#pragma unroll
            for (int rr = 0; rr < 16; rr++) dst[rr * 128] = fold2(acc[rr]);
        } else {
            const int k0 = (g - 5) * 16;
            float* dst = wxo + ((size_t)p4 * 48 + k0) * 128 + b;
#pragma unroll
            for (int rr = 0; rr < 16; rr++)
                dst[rr * 128] = fold2(acc[rr]) + hb_s[k0 + rr];
        }
    }
}

// ---------------------------------------------------------------------------
// qt_final: lat-space only. grid = 4096 (cn*4+q4), 128 thr = kq(4) x col(32).
// ---------------------------------------------------------------------------
__global__ __launch_bounds__(128, 6)
void qt_final(const float* __restrict__ lat4i, const float* __restrict__ f5xi,
              const float* __restrict__ wxi,
              const float* __restrict__ wf, const float* __restrict__ wfa,
              const float* __restrict__ gg,
              float* __restrict__ out)
{
    __shared__ __align__(16) float g_s[16][16];
    __shared__ __align__(16) float wfa_s[48][16];
    __shared__ __align__(16) float wf5_s[4 * 48][16];

    const int bid = blockIdx.x;
    const int cn  = bid >> 2;
    const int q4  = bid & 3;
    const int tid = threadIdx.x;
    const int col = tid & 31;
    const int kq  = tid >> 5;
    const int k0  = kq * 12;

    const int r5 = cn >> 5, c5 = cn & 31;
    const int p4 = (r5 >> 1) * 16 + (c5 >> 1);
    const int b  = q4 * 32 + col;

    {
        if (tid < 64)
            ((float4*)g_s)[tid] = ((const float4*)(gg + (size_t)cn * 256))[tid];
        const float4* sa = (const float4*)(wfa + (size_t)cn * 768);
        float4* da = (float4*)wfa_s;
        for (int i = tid; i < 192; i += 128) da[i] = sa[i];
        const float4* s5 = (const float4*)(wf + (size_t)cn * 3072);
        float4* d5 = (float4*)wf5_s;
        for (int i = tid; i < 768; i += 128) d5[i] = s5[i];
    }

    float l4[16];
    {
        const float* lp = lat4i + (size_t)p4 * 16 * 128 + b;
#pragma unroll
        for (int r = 0; r < 16; r++) l4[r] = __ldg(&lp[r * 128]);
    }
    u64 latq4[8];
#pragma unroll
    for (int j = 0; j < 8; j++) latq4[j] = pack2(l4[2*j], l4[2*j + 1]);

    __syncthreads();

    float l5[16];
    {
        const float* fp = f5xi + (size_t)cn * 16 * 128 + b;
#pragma unroll
        for (int r = 0; r < 16; r++) {
            const ulonglong2* grow = (const ulonglong2*)&g_s[r][0];
            u64 a = 0ull;
#pragma unroll
            for (int j = 0; j < 4; j++) {
                ulonglong2 f = grow[j];
                fma2(a, latq4[2*j],     f.x);
                fma2(a, latq4[2*j + 1], f.y);
            }
            l5[r] = __ldg(&fp[r * 128]) + fold2(a);
        }
    }
    u64 latq5[8];
#pragma unroll
    for (int j = 0; j < 8; j++) latq5[j] = pack2(l5[2*j], l5[2*j + 1]);

    float tk[12];
    {
        const float* wxp = wxi + ((size_t)p4 * 48 + k0) * 128 + b;
#pragma unroll
        for (int kk = 0; kk < 12; kk++) {
            const ulonglong2* ar = (const ulonglong2*)&wfa_s[k0 + kk][0];
            u64 a = 0ull;
#pragma unroll
            for (int j = 0; j < 4; j++) {
                ulonglong2 f = ar[j];
                fma2(a, latq4[2*j],     f.x);
                fma2(a, latq4[2*j + 1], f.y);
            }
            tk[kk] = __ldg(&wxp[kk * 128]) + fold2(a);
        }
    }

#pragma unroll 1
    for (int c = 0; c < 4; c++) {
        const int cn6 = (2 * r5 + (c >> 1)) * 64 + 2 * c5 + (c & 1);

        float acc[12];
#pragma unroll
        for (int kk = 0; kk < 12; kk++) {
            const ulonglong2* wfr = (const ulonglong2*)&wf5_s[c * 48 + k0 + kk][0];
            u64 a = 0ull;
#pragma unroll
            for (int j = 0; j < 4; j++) {
                ulonglong2 f = wfr[j];
                fma2(a, latq5[2*j],     f.x);
                fma2(a, latq5[2*j + 1], f.y);
            }
            acc[kk] = tk[kk] + fold2(a);
        }

        const int sr = cn6 >> 6, sc = cn6 & 63;
#pragma unroll
        for (int oc = 0; oc < 3; oc++) {
            float4 v = make_float4(acc[0 + oc], acc[3 + oc], acc[6 + oc], acc[9 + oc]);
            size_t row = (size_t)(b * 3 + oc) * 256 + (sr * 4 + kq);
            *(float4*)(out + row * 256 + sc * 4) = v;
        }
    }
}

// ---------------------------------------------------------------------------
extern "C" void kernel_launch(void* const* d_in, const int* in_sizes, int n_in,
                              void* d_out, int out_size)
{
    const float* x      = (const float*)d_in[0];
    const float* fin    = (const float*)d_in[1];
    const float* ftl    = (const float*)d_in[2];
    const float* ftr    = (const float*)d_in[3];
    const float* fbl    = (const float*)d_in[4];
    const float* fbr    = (const float*)d_in[5];
    const float* scale  = (const float*)d_in[6];
    const float* head_w = (const float*)d_in[7];
    const float* head_b = (const float*)d_in[8];
    float* out = (float*)d_out;

    float4 *x2, *x4;
    float  *wfb, *wfab, *ggb, *lat4b, *f5xb, *wxb;
    cudaGetSymbolAddress((void**)&x2,    g_x2);
    cudaGetSymbolAddress((void**)&x4,    g_x4);
    cudaGetSymbolAddress((void**)&wfb,   g_wf);
    cudaGetSymbolAddress((void**)&wfab,  g_wfa);
    cudaGetSymbolAddress((void**)&ggb,   g_g);
    cudaGetSymbolAddress((void**)&lat4b, g_lat4);
    cudaGetSymbolAddress((void**)&f5xb,  g_f5x);
    cudaGetSymbolAddress((void**)&wxb,   g_wx);

    qt_prep<<<1024, 256>>>(ftl, ftr, fbl, fbr, fin, scale, head_w, wfb, wfab, ggb);
    qt_l01<<<32,  128>>>(x,  x2, fin, ftl, ftr, fbl, fbr, scale);
    qt_l23<<<512, 128>>>(x2, x4, fin, ftl, ftr, fbl, fbr, scale);
    qt_stack<<<1024, 128>>>(x4, fin, scale, head_w, head_b, lat4b, f5xb, wxb);
    qt_final<<<4096, 128>>>(lat4b, f5xb, wxb, wfb, wfab, ggb, out);
}